// round 15
// baseline (speedup 1.0000x reference)
#include <cuda_runtime.h>
#include <math.h>
#include <float.h>

#define Bq   1024
#define Dd   1024
#define Nn   65536
#define Mm   8
#define KS   256
#define DSs  128
#define OUTn 2048
#define KTOP 64

// ---------------- static device scratch (no dynamic allocation) ----------------
__device__ float g_qa[Bq * Dd];                // 4 MB : q = x @ W
__device__ float g_lut[Bq * Mm * KS];          // 8 MB : lut[b][m][c] = c_sq - 2*cross
__device__ float g_csq[Mm * KS];               // 8 KB
__device__ unsigned long long g_codes[Nn];     // 512 KB : 8 packed u8 codes per n

// ---------------- K0: pack key_codes (N x 8 int32) -> u64 per n ----------------
__global__ void pack_codes_k(const int* __restrict__ kc) {
    int n = blockIdx.x * blockDim.x + threadIdx.x;   // grid exactly N
    unsigned long long v = 0;
#pragma unroll
    for (int m = 0; m < 8; m++)
        v |= (unsigned long long)((unsigned)kc[n * 8 + m] & 255u) << (8 * m);
    g_codes[n] = v;
}

// ---------------- K0b: c_sq[m][c] = ||codebook[m][c]||^2 ----------------
__global__ void csq_k(const float* __restrict__ cb) {
    int g = blockIdx.x * blockDim.x + threadIdx.x;   // 2048 warps exactly
    int w = g >> 5, lane = g & 31;
    const float* r = cb + w * DSs;
    float s = 0.f;
#pragma unroll
    for (int d = lane; d < DSs; d += 32) { float x = r[d]; s = fmaf(x, x, s); }
#pragma unroll
    for (int o = 16; o; o >>= 1) s += __shfl_xor_sync(0xffffffffu, s, o);
    if (lane == 0) g_csq[w] = s;
}

// ================= 3xTF32 tensor-core mma helpers =================
__device__ __forceinline__ unsigned f2tf(float x) {
    unsigned r;
    asm("cvt.rna.tf32.f32 %0, %1;" : "=r"(r) : "f"(x));
    return r;
}

#define MMA_TF32(c, a, b0v, b1v)                                             \
    asm volatile("mma.sync.aligned.m16n8k8.row.col.f32.tf32.tf32.f32 "       \
        "{%0,%1,%2,%3}, {%4,%5,%6,%7}, {%8,%9}, {%0,%1,%2,%3};"              \
        : "+f"((c)[0]), "+f"((c)[1]), "+f"((c)[2]), "+f"((c)[3])             \
        : "r"((a)[0]), "r"((a)[1]), "r"((a)[2]), "r"((a)[3]),                \
          "r"(b0v), "r"(b1v))

#define A_STRIDE 20
#define B_STRIDE 72

// ================= K1: q = x @ W via 3xTF32 mma =================
__global__ void __launch_bounds__(128) gemm_tc(const float* __restrict__ A,
                                               const float* __restrict__ W) {
    __shared__ unsigned Ah[64 * A_STRIDE], Al[64 * A_STRIDE];   // [m][k] pad 20
    __shared__ unsigned Bh[16 * B_STRIDE], Bl[16 * B_STRIDE];   // [k][n] pad 72
    int tid  = threadIdx.x;
    int lane = tid & 31;
    int w    = tid >> 5;
    int m0 = blockIdx.y * 64;
    int n0 = blockIdx.x * 64;
    int wm = (w & 1) * 32;          // warp tile 32x32
    int wn = (w >> 1) * 32;

    float c[2][4][4];
#pragma unroll
    for (int mt = 0; mt < 2; mt++)
#pragma unroll
        for (int nt = 0; nt < 4; nt++)
#pragma unroll
            for (int r = 0; r < 4; r++) c[mt][nt][r] = 0.f;

    int ar = tid >> 2, aq = (tid & 3) * 4;     // A: 32 rows/pass, 4 k-floats
    int br = tid >> 4, bq = (tid & 15) * 4;    // B: 8 rows/pass, 4 n-floats

    for (int k0 = 0; k0 < Dd; k0 += 16) {
#pragma unroll
        for (int p = 0; p < 2; p++) {
            int r = ar + p * 32;
            float4 v = *(const float4*)&A[(m0 + r) * Dd + k0 + aq];
            unsigned h0 = f2tf(v.x), h1 = f2tf(v.y), h2 = f2tf(v.z), h3 = f2tf(v.w);
            unsigned l0 = f2tf(v.x - __uint_as_float(h0));
            unsigned l1 = f2tf(v.y - __uint_as_float(h1));
            unsigned l2 = f2tf(v.z - __uint_as_float(h2));
            unsigned l3 = f2tf(v.w - __uint_as_float(h3));
            int base = r * A_STRIDE + aq;
            Ah[base + 0] = h0; Ah[base + 1] = h1; Ah[base + 2] = h2; Ah[base + 3] = h3;
            Al[base + 0] = l0; Al[base + 1] = l1; Al[base + 2] = l2; Al[base + 3] = l3;
        }
#pragma unroll
        for (int p = 0; p < 2; p++) {
            int r = br + p * 8;
            float4 v = *(const float4*)&W[(k0 + r) * Dd + n0 + bq];
            unsigned h0 = f2tf(v.x), h1 = f2tf(v.y), h2 = f2tf(v.z), h3 = f2tf(v.w);
            unsigned l0 = f2tf(v.x - __uint_as_float(h0));
            unsigned l1 = f2tf(v.y - __uint_as_float(h1));
            unsigned l2 = f2tf(v.z - __uint_as_float(h2));
            unsigned l3 = f2tf(v.w - __uint_as_float(h3));
            int base = r * B_STRIDE + bq;
            Bh[base + 0] = h0; Bh[base + 1] = h1; Bh[base + 2] = h2; Bh[base + 3] = h3;
            Bl[base + 0] = l0; Bl[base + 1] = l1; Bl[base + 2] = l2; Bl[base + 3] = l3;
        }
        __syncthreads();

#pragma unroll
        for (int ks = 0; ks < 2; ks++) {
            int kb = ks * 8;
            unsigned ah[2][4], al[2][4];
#pragma unroll
            for (int mt = 0; mt < 2; mt++) {
                int r0 = wm + mt * 16 + (lane >> 2);
                int k  = kb + (lane & 3);
                ah[mt][0] = Ah[ r0      * A_STRIDE + k    ];
                ah[mt][1] = Ah[(r0 + 8) * A_STRIDE + k    ];
                ah[mt][2] = Ah[ r0      * A_STRIDE + k + 4];
                ah[mt][3] = Ah[(r0 + 8) * A_STRIDE + k + 4];
                al[mt][0] = Al[ r0      * A_STRIDE + k    ];
                al[mt][1] = Al[(r0 + 8) * A_STRIDE + k    ];
                al[mt][2] = Al[ r0      * A_STRIDE + k + 4];
                al[mt][3] = Al[(r0 + 8) * A_STRIDE + k + 4];
            }
#pragma unroll
            for (int nt = 0; nt < 4; nt++) {
                int cb = wn + nt * 8 + (lane >> 2);
                int kr = kb + (lane & 3);
                unsigned bh0 = Bh[ kr      * B_STRIDE + cb];
                unsigned bh1 = Bh[(kr + 4) * B_STRIDE + cb];
                unsigned bl0 = Bl[ kr      * B_STRIDE + cb];
                unsigned bl1 = Bl[(kr + 4) * B_STRIDE + cb];
#pragma unroll
                for (int mt = 0; mt < 2; mt++) {
                    MMA_TF32(c[mt][nt], ah[mt], bh0, bh1);   // hi*hi
                    MMA_TF32(c[mt][nt], ah[mt], bl0, bl1);   // hi*lo
                    MMA_TF32(c[mt][nt], al[mt], bh0, bh1);   // lo*hi
                }
            }
        }
        __syncthreads();
    }

    // epilogue: D m16n8 layout -> g_qa
#pragma unroll
    for (int mt = 0; mt < 2; mt++)
#pragma unroll
        for (int nt = 0; nt < 4; nt++) {
            int row = m0 + wm + mt * 16 + (lane >> 2);
            int col = n0 + wn + nt * 8 + (lane & 3) * 2;
            *(float2*)&g_qa[row * Dd + col]       = make_float2(c[mt][nt][0], c[mt][nt][1]);
            *(float2*)&g_qa[(row + 8) * Dd + col] = make_float2(c[mt][nt][2], c[mt][nt][3]);
        }
}

// ================= K2: lut via 3xTF32 mma =================
__global__ void __launch_bounds__(128) lut_mma(const float* __restrict__ cbk) {
    __shared__ unsigned Ah[64 * A_STRIDE], Al[64 * A_STRIDE];   // q tile   [row][k] pad 20
    __shared__ unsigned Ch[64 * A_STRIDE], Cl[64 * A_STRIDE];   // cb tile  [c][k]   pad 20
    int tid  = threadIdx.x;
    int lane = tid & 31;
    int w    = tid >> 5;
    int m  = blockIdx.z;
    int b0 = blockIdx.y * 64;
    int c0 = blockIdx.x * 64;
    int wm = (w & 1) * 32;
    int wn = (w >> 1) * 32;

    float c[2][4][4];
#pragma unroll
    for (int mt = 0; mt < 2; mt++)
#pragma unroll
        for (int nt = 0; nt < 4; nt++)
#pragma unroll
            for (int r = 0; r < 4; r++) c[mt][nt][r] = 0.f;

    int ar = tid >> 2, aq = (tid & 3) * 4;     // 32 rows/pass, 4 k-floats/thread
    const float* cbm = cbk + m * KS * DSs;

    for (int k0 = 0; k0 < DSs; k0 += 16) {
#pragma unroll
        for (int p = 0; p < 2; p++) {
            int r = ar + p * 32;
            float4 v = *(const float4*)&g_qa[(b0 + r) * Dd + m * DSs + k0 + aq];
            unsigned h0 = f2tf(v.x), h1 = f2tf(v.y), h2 = f2tf(v.z), h3 = f2tf(v.w);
            unsigned l0 = f2tf(v.x - __uint_as_float(h0));
            unsigned l1 = f2tf(v.y - __uint_as_float(h1));
            unsigned l2 = f2tf(v.z - __uint_as_float(h2));
            unsigned l3 = f2tf(v.w - __uint_as_float(h3));
            int base = r * A_STRIDE + aq;
            Ah[base + 0] = h0; Ah[base + 1] = h1; Ah[base + 2] = h2; Ah[base + 3] = h3;
            Al[base + 0] = l0; Al[base + 1] = l1; Al[base + 2] = l2; Al[base + 3] = l3;
            float4 u = *(const float4*)&cbm[(c0 + r) * DSs + k0 + aq];
            unsigned g0 = f2tf(u.x), g1 = f2tf(u.y), g2 = f2tf(u.z), g3 = f2tf(u.w);
            unsigned e0 = f2tf(u.x - __uint_as_float(g0));
            unsigned e1 = f2tf(u.y - __uint_as_float(g1));
            unsigned e2 = f2tf(u.z - __uint_as_float(g2));
            unsigned e3 = f2tf(u.w - __uint_as_float(g3));
            Ch[base + 0] = g0; Ch[base + 1] = g1; Ch[base + 2] = g2; Ch[base + 3] = g3;
            Cl[base + 0] = e0; Cl[base + 1] = e1; Cl[base + 2] = e2; Cl[base + 3] = e3;
        }
        __syncthreads();

#pragma unroll
        for (int ks = 0; ks < 2; ks++) {
            int kb = ks * 8;
            unsigned ah[2][4], al[2][4];
#pragma unroll
            for (int mt = 0; mt < 2; mt++) {
                int r0 = wm + mt * 16 + (lane >> 2);
                int k  = kb + (lane & 3);
                ah[mt][0] = Ah[ r0      * A_STRIDE + k    ];
                ah[mt][1] = Ah[(r0 + 8) * A_STRIDE + k    ];
                ah[mt][2] = Ah[ r0      * A_STRIDE + k + 4];
                ah[mt][3] = Ah[(r0 + 8) * A_STRIDE + k + 4];
                al[mt][0] = Al[ r0      * A_STRIDE + k    ];
                al[mt][1] = Al[(r0 + 8) * A_STRIDE + k    ];
                al[mt][2] = Al[ r0      * A_STRIDE + k + 4];
                al[mt][3] = Al[(r0 + 8) * A_STRIDE + k + 4];
            }
#pragma unroll
            for (int nt = 0; nt < 4; nt++) {
                int cc = wn + nt * 8 + (lane >> 2);
                int kr = kb + (lane & 3);
                unsigned bh0 = Ch[cc * A_STRIDE + kr    ];
                unsigned bh1 = Ch[cc * A_STRIDE + kr + 4];
                unsigned bl0 = Cl[cc * A_STRIDE + kr    ];
                unsigned bl1 = Cl[cc * A_STRIDE + kr + 4];
#pragma unroll
                for (int mt = 0; mt < 2; mt++) {
                    MMA_TF32(c[mt][nt], ah[mt], bh0, bh1);
                    MMA_TF32(c[mt][nt], ah[mt], bl0, bl1);
                    MMA_TF32(c[mt][nt], al[mt], bh0, bh1);
                }
            }
        }
        __syncthreads();
    }

    // epilogue: lut = csq - 2*cross
#pragma unroll
    for (int mt = 0; mt < 2; mt++)
#pragma unroll
        for (int nt = 0; nt < 4; nt++) {
            int row = b0 + wm + mt * 16 + (lane >> 2);
            int col = c0 + wn + nt * 8 + (lane & 3) * 2;
            float2 s = *(const float2*)&g_csq[m * KS + col];
            *(float2*)&g_lut[row * OUTn + m * KS + col] =
                make_float2(s.x - 2.f * c[mt][nt][0], s.y - 2.f * c[mt][nt][1]);
            *(float2*)&g_lut[(row + 8) * OUTn + m * KS + col] =
                make_float2(s.x - 2.f * c[mt][nt][2], s.y - 2.f * c[mt][nt][3]);
        }
}

// ================= register/shfl bitonic top-64 machinery =================
__device__ __forceinline__ void cx_shfl(float& v, int& i, int lane, int ehi, int k, int j) {
    float pv = __shfl_xor_sync(0xffffffffu, v, j);
    int   pi = __shfl_xor_sync(0xffffffffu, i, j);
    bool up = (((ehi + lane) & k) == 0);
    bool keep_min = (up == ((lane & j) == 0));
    if ((pv < v) == keep_min) { v = pv; i = pi; }
}

__device__ __forceinline__ void sort64(float& v0, int& i0, float& v1, int& i1, int lane) {
#pragma unroll
    for (int k = 2; k <= 32; k <<= 1) {
#pragma unroll
        for (int j = k >> 1; j >= 1; j >>= 1) {
            cx_shfl(v0, i0, lane, 0, k, j);
            cx_shfl(v1, i1, lane, 32, k, j);
        }
    }
    if (v1 < v0) { float t = v0; v0 = v1; v1 = t; int ti = i0; i0 = i1; i1 = ti; }
#pragma unroll
    for (int j = 16; j >= 1; j >>= 1) {
        cx_shfl(v0, i0, lane, 0, 64, j);
        cx_shfl(v1, i1, lane, 32, 64, j);
    }
}

__device__ __forceinline__ void merge64(float& k0v, int& k0i, float& k1v, int& k1i,
                                        float b0v, int b0i, float b1v, int b1i, int lane) {
    float r0v = __shfl_xor_sync(0xffffffffu, b1v, 31);
    int   r0i = __shfl_xor_sync(0xffffffffu, b1i, 31);
    float r1v = __shfl_xor_sync(0xffffffffu, b0v, 31);
    int   r1i = __shfl_xor_sync(0xffffffffu, b0i, 31);
    if (r0v < k0v) { k0v = r0v; k0i = r0i; }
    if (r1v < k1v) { k1v = r1v; k1i = r1i; }
    if (k1v < k0v) { float t = k0v; k0v = k1v; k1v = t; int ti = k0i; k0i = k1i; k1i = ti; }
#pragma unroll
    for (int j = 16; j >= 1; j >>= 1) {
        cx_shfl(k0v, k0i, lane, 0, 64, j);
        cx_shfl(k1v, k1i, lane, 32, 64, j);
    }
}

// flush: sort 64-candidate batch from smem buffer, merge into register kept list
__device__ __forceinline__ void flush_batch(float* mbd, int* mbi, int& cnt, float& tau,
                                            float& k0v, int& k0i, float& k1v, int& k1i,
                                            int lane) {
    __syncwarp();
    float b0v = mbd[lane], b1v = mbd[32 + lane];
    int   b0i = mbi[lane], b1i = mbi[32 + lane];
    int left = cnt - 64;
    if (lane < left) { mbd[lane] = mbd[64 + lane]; mbi[lane] = mbi[64 + lane]; }
    cnt = left;
    __syncwarp();
    sort64(b0v, b0i, b1v, b1i, lane);
    merge64(k0v, k0i, k1v, k1i, b0v, b0i, b1v, b1i, lane);
    tau = __shfl_sync(0xffffffffu, k1v, 31);
}

// ---------------- K3: warp-autonomous PQ scan, 2 rows per CTA, float2 LUT ----------------
__global__ void __launch_bounds__(512, 2) scan2_k(const int* __restrict__ vcodes,
                                                  const float* __restrict__ vcb,
                                                  const float* __restrict__ bias,
                                                  float* __restrict__ out) {
    int b0 = blockIdx.x * 2;
    int tid = threadIdx.x;
    int lane = tid & 31;
    int w = tid >> 5;                    // 16 warps
    __shared__ float2 lut2[2048];        // 16 KB : rows (b0, b0+1) interleaved
    __shared__ float bufd[16 * 2 * 96];  // 12 KB : per-warp, per-row candidate buffers
    __shared__ int   bufi[16 * 2 * 96];  // 12 KB
    __shared__ float s_w[2][KTOP];
    __shared__ float s_winv[2];

    // stage both LUT rows interleaved
    for (int i = tid; i < 2048; i += 512)
        lut2[i] = make_float2(g_lut[b0 * 2048 + i], g_lut[b0 * 2048 + 2048 + i]);
    __syncthreads();

    float* mbdA = bufd + (w * 2 + 0) * 96;
    int*   mbiA = bufi + (w * 2 + 0) * 96;
    float* mbdB = bufd + (w * 2 + 1) * 96;
    int*   mbiB = bufi + (w * 2 + 1) * 96;
    int   cntA = 0, cntB = 0;
    float tauA = FLT_MAX, tauB = FLT_MAX;
    float k0vA = FLT_MAX, k1vA = FLT_MAX, k0vB = FLT_MAX, k1vB = FLT_MAX;
    int   k0iA = 0, k1iA = 0, k0iB = 0, k1iB = 0;
    unsigned lanemask_lt = (1u << lane) - 1u;

    int nbase = w << 12;                 // warp stripe: 4096 codes
    unsigned long long c8 = g_codes[nbase + lane];
#pragma unroll 1
    for (int it = 0; it < 128; ++it) {
        int n = nbase + (it << 5) + lane;
        unsigned long long nx = (it < 127) ? g_codes[n + 32] : 0ULL;
        unsigned lo = (unsigned)c8;
        unsigned hi = (unsigned)(c8 >> 32);
        float2 v0 = lut2[          (lo         & 255u)];
        float2 v1 = lut2[ 256 + ((lo >>  8) & 255u)];
        float2 v2 = lut2[ 512 + ((lo >> 16) & 255u)];
        float2 v3 = lut2[ 768 +  (lo >> 24)         ];
        float2 v4 = lut2[1024 + ( hi         & 255u)];
        float2 v5 = lut2[1280 + ((hi >>  8) & 255u)];
        float2 v6 = lut2[1536 + ((hi >> 16) & 255u)];
        float2 v7 = lut2[1792 +  (hi >> 24)         ];
        float dA = ((v0.x + v1.x) + (v2.x + v3.x)) + ((v4.x + v5.x) + (v6.x + v7.x));
        float dB = ((v0.y + v1.y) + (v2.y + v3.y)) + ((v4.y + v5.y) + (v6.y + v7.y));
        c8 = nx;
        unsigned ballA = __ballot_sync(0xffffffffu, dA < tauA);
        if (dA < tauA) {
            int pos = cntA + __popc(ballA & lanemask_lt);
            mbdA[pos] = dA; mbiA[pos] = n;
        }
        cntA += __popc(ballA);
        unsigned ballB = __ballot_sync(0xffffffffu, dB < tauB);
        if (dB < tauB) {
            int pos = cntB + __popc(ballB & lanemask_lt);
            mbdB[pos] = dB; mbiB[pos] = n;
        }
        cntB += __popc(ballB);
        if (cntA >= 64) flush_batch(mbdA, mbiA, cntA, tauA, k0vA, k0iA, k1vA, k1iA, lane);
        if (cntB >= 64) flush_batch(mbdB, mbiB, cntB, tauB, k0vB, k0iB, k1vB, k1iB, lane);
    }
    // final partial flushes
    if (cntA > 0) {
        for (int i2 = cntA + lane; i2 < 64; i2 += 32) mbdA[i2] = FLT_MAX;
        __syncwarp();
        float b0v = mbdA[lane], b1v = mbdA[32 + lane];
        int   b0i = mbiA[lane], b1i = mbiA[32 + lane];
        sort64(b0v, b0i, b1v, b1i, lane);
        merge64(k0vA, k0iA, k1vA, k1iA, b0v, b0i, b1v, b1i, lane);
    }
    if (cntB > 0) {
        for (int i2 = cntB + lane; i2 < 64; i2 += 32) mbdB[i2] = FLT_MAX;
        __syncwarp();
        float b0v = mbdB[lane], b1v = mbdB[32 + lane];
        int   b0i = mbiB[lane], b1i = mbiB[32 + lane];
        sort64(b0v, b0i, b1v, b1i, lane);
        merge64(k0vB, k0iB, k1vB, k1iB, b0v, b0i, b1v, b1i, lane);
    }
    // publish both sorted top-64 lists
    mbdA[lane] = k0vA;  mbdA[32 + lane] = k1vA;
    mbiA[lane] = k0iA;  mbiA[32 + lane] = k1iA;
    mbdB[lane] = k0vB;  mbdB[32 + lane] = k1vB;
    mbiB[lane] = k0iB;  mbiB[32 + lane] = k1iB;
    __syncthreads();

    // two concurrent tournaments: warps 0-7 merge row 0 lists, warps 8-15 row 1
    int tb = w >> 3, tj = w & 7;
#pragma unroll
    for (int step = 1; step < 16; step <<= 1) {
        if (tj * 2 * step < 16) {
            int ia = tj * 2 * step, ib = ia + step;
            int la = (ia * 2 + tb) * 96, lb = (ib * 2 + tb) * 96;
            float a0 = bufd[la + lane], a1 = bufd[la + 32 + lane];
            int   x0 = bufi[la + lane], x1 = bufi[la + 32 + lane];
            float c0 = bufd[lb + lane], c1 = bufd[lb + 32 + lane];
            int   y0 = bufi[lb + lane], y1 = bufi[lb + 32 + lane];
            merge64(a0, x0, a1, x1, c0, y0, c1, y1, lane);
            bufd[la + lane] = a0;  bufd[la + 32 + lane] = a1;
            bufi[la + lane] = x0;  bufi[la + 32 + lane] = x1;
        }
        __syncthreads();
    }
    // row bb final top-64 at bufd[bb*96 + 0..63]

    // softmax weights for both rows
    if (tid < 2 * KTOP) {
        int bb = tid >> 6, kk = tid & 63;
        const float* cd = bufd + bb * 96;
        s_w[bb][kk] = expf(cd[0] - cd[kk]);
    }
    __syncthreads();
    if (tid < 2) {
        float s = 0.f;
        for (int i = 0; i < KTOP; i++) s += s_w[tid][i];
        s_winv[tid] = 1.0f / s;
    }
    __syncthreads();

    // output both rows
#pragma unroll 1
    for (int bb = 0; bb < 2; bb++) {
        const int* ci = bufi + bb * 96;
        int o0   = tid << 2;          // 4 outputs per thread
        int mv   = tid >> 6;          // warp-uniform
        int col4 = (o0 & 255) >> 2;
        float4 acc = *(const float4*)&bias[o0];
        const float4* vcb4 = (const float4*)vcb;
        float winv = s_winv[bb];
#pragma unroll 4
        for (int kk = 0; kk < KTOP; kk++) {
            int n = ci[kk];
            float wt = s_w[bb][kk] * winv;
            int code = vcodes[n * 8 + mv];
            float4 v = vcb4[(((mv << 8) + code) << 6) + col4];
            acc.x = fmaf(wt, v.x, acc.x);
            acc.y = fmaf(wt, v.y, acc.y);
            acc.z = fmaf(wt, v.z, acc.z);
            acc.w = fmaf(wt, v.w, acc.w);
        }
        *(float4*)&out[(b0 + bb) * OUTn + o0] = acc;
    }
}

// ---------------- launch ----------------
extern "C" void kernel_launch(void* const* d_in, const int* in_sizes, int n_in,
                              void* d_out, int out_size) {
    const float* x    = (const float*)d_in[0];   // (B, D)
    const float* W    = (const float*)d_in[1];   // (D, D)
    const float* kcb  = (const float*)d_in[2];   // (M, Ks, DS)
    const float* vcb  = (const float*)d_in[3];   // (MV, Ks, DV)
    const float* bias = (const float*)d_in[4];   // (OUT,)
    const int*   kc   = (const int*)d_in[5];     // (N, M)
    const int*   vc   = (const int*)d_in[6];     // (N, MV)
    float* out = (float*)d_out;                  // (B, OUT)

    pack_codes_k<<<Nn / 256, 256>>>(kc);
    csq_k<<<(Mm * KS * 32) / 256, 256>>>(kcb);
    gemm_tc<<<dim3(Dd / 64, Bq / 64), 128>>>(x, W);
    lut_mma<<<dim3(KS / 64, Bq / 64, Mm), 128>>>(kcb);
    scan2_k<<<Bq / 2, 512>>>(vc, vcb, bias, out);
}

// round 16
// speedup vs baseline: 1.0355x; 1.0355x over previous
#include <cuda_runtime.h>
#include <math.h>
#include <float.h>

#define Bq   1024
#define Dd   1024
#define Nn   65536
#define Mm   8
#define KS   256
#define DSs  128
#define OUTn 2048
#define KTOP 64

// ---------------- static device scratch (no dynamic allocation) ----------------
__device__ float g_qa[Bq * Dd];                // 4 MB : q = x @ W
__device__ float g_lut[Bq * Mm * KS];          // 8 MB : lut[b][m][c] = c_sq - 2*cross
__device__ float g_csq[Mm * KS];               // 8 KB
__device__ unsigned long long g_codes[Nn];     // 512 KB : 8 packed u8 codes per n

// ---------------- K0: pack key_codes (N x 8 int32) -> u64 per n ----------------
__global__ void pack_codes_k(const int* __restrict__ kc) {
    int n = blockIdx.x * blockDim.x + threadIdx.x;   // grid exactly N
    unsigned long long v = 0;
#pragma unroll
    for (int m = 0; m < 8; m++)
        v |= (unsigned long long)((unsigned)kc[n * 8 + m] & 255u) << (8 * m);
    g_codes[n] = v;
}

// ---------------- K0b: c_sq[m][c] = ||codebook[m][c]||^2 ----------------
__global__ void csq_k(const float* __restrict__ cb) {
    int g = blockIdx.x * blockDim.x + threadIdx.x;   // 2048 warps exactly
    int w = g >> 5, lane = g & 31;
    const float* r = cb + w * DSs;
    float s = 0.f;
#pragma unroll
    for (int d = lane; d < DSs; d += 32) { float x = r[d]; s = fmaf(x, x, s); }
#pragma unroll
    for (int o = 16; o; o >>= 1) s += __shfl_xor_sync(0xffffffffu, s, o);
    if (lane == 0) g_csq[w] = s;
}

// ================= 3xTF32 tensor-core mma helpers =================
__device__ __forceinline__ unsigned f2tf(float x) {
    unsigned r;
    asm("cvt.rna.tf32.f32 %0, %1;" : "=r"(r) : "f"(x));
    return r;
}

__device__ __forceinline__ uint2 split_tf(float x) {
    unsigned h = f2tf(x);
    unsigned l = f2tf(x - __uint_as_float(h));
    return make_uint2(h, l);
}

#define MMA_TF32(c, a, b0v, b1v)                                             \
    asm volatile("mma.sync.aligned.m16n8k8.row.col.f32.tf32.tf32.f32 "       \
        "{%0,%1,%2,%3}, {%4,%5,%6,%7}, {%8,%9}, {%0,%1,%2,%3};"              \
        : "+f"((c)[0]), "+f"((c)[1]), "+f"((c)[2]), "+f"((c)[3])             \
        : "r"((a)[0]), "r"((a)[1]), "r"((a)[2]), "r"((a)[3]),                \
          "r"(b0v), "r"(b1v))

#define AST 20   // uint2 row stride for [64][16+pad] tiles (word stride 40 ≡ 8 mod 32)
#define BST 68   // uint2 row stride for [16][64+pad] tile  (word stride 136 ≡ 8 mod 32)

// ================= K1: q = x @ W via 3xTF32 mma, hi/lo interleaved + prefetch =================
__global__ void __launch_bounds__(128) gemm_tc(const float* __restrict__ A,
                                               const float* __restrict__ W) {
    __shared__ uint2 A2[64 * AST];   // [m][k] {hi,lo}
    __shared__ uint2 B2[16 * BST];   // [k][n] {hi,lo}
    int tid  = threadIdx.x;
    int lane = tid & 31;
    int w    = tid >> 5;
    int m0 = blockIdx.y * 64;
    int n0 = blockIdx.x * 64;
    int wm = (w & 1) * 32;          // warp tile 32x32
    int wn = (w >> 1) * 32;

    float c[2][4][4];
#pragma unroll
    for (int mt = 0; mt < 2; mt++)
#pragma unroll
        for (int nt = 0; nt < 4; nt++)
#pragma unroll
            for (int r = 0; r < 4; r++) c[mt][nt][r] = 0.f;

    int ar = tid >> 2, aq = (tid & 3) * 4;     // A: 32 rows/pass, 4 k-floats
    int br = tid >> 4, bq = (tid & 15) * 4;    // B: 8 rows/pass, 4 n-floats

    // prefetch k0 = 0
    float4 vA[2], vB[2];
#pragma unroll
    for (int p = 0; p < 2; p++) {
        vA[p] = *(const float4*)&A[(m0 + ar + p * 32) * Dd + aq];
        vB[p] = *(const float4*)&W[(br + p * 8) * Dd + n0 + bq];
    }

    for (int k0 = 0; k0 < Dd; k0 += 16) {
        float4 nA[2], nB[2];
        if (k0 + 16 < Dd) {
#pragma unroll
            for (int p = 0; p < 2; p++) {
                nA[p] = *(const float4*)&A[(m0 + ar + p * 32) * Dd + k0 + 16 + aq];
                nB[p] = *(const float4*)&W[(k0 + 16 + br + p * 8) * Dd + n0 + bq];
            }
        }
#pragma unroll
        for (int p = 0; p < 2; p++) {
            float4 v = vA[p];
            int base = (ar + p * 32) * AST + aq;
            A2[base + 0] = split_tf(v.x);
            A2[base + 1] = split_tf(v.y);
            A2[base + 2] = split_tf(v.z);
            A2[base + 3] = split_tf(v.w);
            float4 u = vB[p];
            int bbase = (br + p * 8) * BST + bq;
            B2[bbase + 0] = split_tf(u.x);
            B2[bbase + 1] = split_tf(u.y);
            B2[bbase + 2] = split_tf(u.z);
            B2[bbase + 3] = split_tf(u.w);
        }
        __syncthreads();

#pragma unroll
        for (int ks = 0; ks < 2; ks++) {
            int kb = ks * 8;
            unsigned ah[2][4], al[2][4];
#pragma unroll
            for (int mt = 0; mt < 2; mt++) {
                int r0 = wm + mt * 16 + (lane >> 2);
                int k  = kb + (lane & 3);
                uint2 p0 = A2[ r0      * AST + k    ];
                uint2 p1 = A2[(r0 + 8) * AST + k    ];
                uint2 p2 = A2[ r0      * AST + k + 4];
                uint2 p3 = A2[(r0 + 8) * AST + k + 4];
                ah[mt][0] = p0.x; al[mt][0] = p0.y;
                ah[mt][1] = p1.x; al[mt][1] = p1.y;
                ah[mt][2] = p2.x; al[mt][2] = p2.y;
                ah[mt][3] = p3.x; al[mt][3] = p3.y;
            }
#pragma unroll
            for (int nt = 0; nt < 4; nt++) {
                int cb = wn + nt * 8 + (lane >> 2);
                int kr = kb + (lane & 3);
                uint2 q0 = B2[ kr      * BST + cb];
                uint2 q1 = B2[(kr + 4) * BST + cb];
#pragma unroll
                for (int mt = 0; mt < 2; mt++) {
                    MMA_TF32(c[mt][nt], ah[mt], q0.x, q1.x);   // hi*hi
                    MMA_TF32(c[mt][nt], ah[mt], q0.y, q1.y);   // hi*lo
                    MMA_TF32(c[mt][nt], al[mt], q0.x, q1.x);   // lo*hi
                }
            }
        }
        __syncthreads();
#pragma unroll
        for (int p = 0; p < 2; p++) { vA[p] = nA[p]; vB[p] = nB[p]; }
    }

    // epilogue: D m16n8 layout -> g_qa
#pragma unroll
    for (int mt = 0; mt < 2; mt++)
#pragma unroll
        for (int nt = 0; nt < 4; nt++) {
            int row = m0 + wm + mt * 16 + (lane >> 2);
            int col = n0 + wn + nt * 8 + (lane & 3) * 2;
            *(float2*)&g_qa[row * Dd + col]       = make_float2(c[mt][nt][0], c[mt][nt][1]);
            *(float2*)&g_qa[(row + 8) * Dd + col] = make_float2(c[mt][nt][2], c[mt][nt][3]);
        }
}

// ================= K2: lut via 3xTF32 mma, hi/lo interleaved + prefetch =================
__global__ void __launch_bounds__(128) lut_mma(const float* __restrict__ cbk) {
    __shared__ uint2 A2[64 * AST];   // q tile  [row][k] {hi,lo}
    __shared__ uint2 C2[64 * AST];   // cb tile [c][k]   {hi,lo}
    int tid  = threadIdx.x;
    int lane = tid & 31;
    int w    = tid >> 5;
    int m  = blockIdx.z;
    int b0 = blockIdx.y * 64;
    int c0 = blockIdx.x * 64;
    int wm = (w & 1) * 32;
    int wn = (w >> 1) * 32;

    float c[2][4][4];
#pragma unroll
    for (int mt = 0; mt < 2; mt++)
#pragma unroll
        for (int nt = 0; nt < 4; nt++)
#pragma unroll
            for (int r = 0; r < 4; r++) c[mt][nt][r] = 0.f;

    int ar = tid >> 2, aq = (tid & 3) * 4;     // 32 rows/pass, 4 k-floats/thread
    const float* cbm = cbk + m * KS * DSs;

    // prefetch k0 = 0
    float4 vQ[2], vC[2];
#pragma unroll
    for (int p = 0; p < 2; p++) {
        vQ[p] = *(const float4*)&g_qa[(b0 + ar + p * 32) * Dd + m * DSs + aq];
        vC[p] = *(const float4*)&cbm[(c0 + ar + p * 32) * DSs + aq];
    }

    for (int k0 = 0; k0 < DSs; k0 += 16) {
        float4 nQ[2], nC[2];
        if (k0 + 16 < DSs) {
#pragma unroll
            for (int p = 0; p < 2; p++) {
                nQ[p] = *(const float4*)&g_qa[(b0 + ar + p * 32) * Dd + m * DSs + k0 + 16 + aq];
                nC[p] = *(const float4*)&cbm[(c0 + ar + p * 32) * DSs + k0 + 16 + aq];
            }
        }
#pragma unroll
        for (int p = 0; p < 2; p++) {
            int base = (ar + p * 32) * AST + aq;
            float4 v = vQ[p];
            A2[base + 0] = split_tf(v.x);
            A2[base + 1] = split_tf(v.y);
            A2[base + 2] = split_tf(v.z);
            A2[base + 3] = split_tf(v.w);
            float4 u = vC[p];
            C2[base + 0] = split_tf(u.x);
            C2[base + 1] = split_tf(u.y);
            C2[base + 2] = split_tf(u.z);
            C2[base + 3] = split_tf(u.w);
        }
        __syncthreads();

#pragma unroll
        for (int ks = 0; ks < 2; ks++) {
            int kb = ks * 8;
            unsigned ah[2][4], al[2][4];
#pragma unroll
            for (int mt = 0; mt < 2; mt++) {
                int r0 = wm + mt * 16 + (lane >> 2);
                int k  = kb + (lane & 3);
                uint2 p0 = A2[ r0      * AST + k    ];
                uint2 p1 = A2[(r0 + 8) * AST + k    ];
                uint2 p2 = A2[ r0      * AST + k + 4];
                uint2 p3 = A2[(r0 + 8) * AST + k + 4];
                ah[mt][0] = p0.x; al[mt][0] = p0.y;
                ah[mt][1] = p1.x; al[mt][1] = p1.y;
                ah[mt][2] = p2.x; al[mt][2] = p2.y;
                ah[mt][3] = p3.x; al[mt][3] = p3.y;
            }
#pragma unroll
            for (int nt = 0; nt < 4; nt++) {
                int cc = wn + nt * 8 + (lane >> 2);
                int kr = kb + (lane & 3);
                uint2 q0 = C2[cc * AST + kr    ];
                uint2 q1 = C2[cc * AST + kr + 4];
#pragma unroll
                for (int mt = 0; mt < 2; mt++) {
                    MMA_TF32(c[mt][nt], ah[mt], q0.x, q1.x);
                    MMA_TF32(c[mt][nt], ah[mt], q0.y, q1.y);
                    MMA_TF32(c[mt][nt], al[mt], q0.x, q1.x);
                }
            }
        }
        __syncthreads();
#pragma unroll
        for (int p = 0; p < 2; p++) { vQ[p] = nQ[p]; vC[p] = nC[p]; }
    }

    // epilogue: lut = csq - 2*cross
#pragma unroll
    for (int mt = 0; mt < 2; mt++)
#pragma unroll
        for (int nt = 0; nt < 4; nt++) {
            int row = b0 + wm + mt * 16 + (lane >> 2);
            int col = c0 + wn + nt * 8 + (lane & 3) * 2;
            float2 s = *(const float2*)&g_csq[m * KS + col];
            *(float2*)&g_lut[row * OUTn + m * KS + col] =
                make_float2(s.x - 2.f * c[mt][nt][0], s.y - 2.f * c[mt][nt][1]);
            *(float2*)&g_lut[(row + 8) * OUTn + m * KS + col] =
                make_float2(s.x - 2.f * c[mt][nt][2], s.y - 2.f * c[mt][nt][3]);
        }
}

// ================= register/shfl bitonic top-64 machinery =================
__device__ __forceinline__ void cx_shfl(float& v, int& i, int lane, int ehi, int k, int j) {
    float pv = __shfl_xor_sync(0xffffffffu, v, j);
    int   pi = __shfl_xor_sync(0xffffffffu, i, j);
    bool up = (((ehi + lane) & k) == 0);
    bool keep_min = (up == ((lane & j) == 0));
    if ((pv < v) == keep_min) { v = pv; i = pi; }
}

__device__ __forceinline__ void sort64(float& v0, int& i0, float& v1, int& i1, int lane) {
#pragma unroll
    for (int k = 2; k <= 32; k <<= 1) {
#pragma unroll
        for (int j = k >> 1; j >= 1; j >>= 1) {
            cx_shfl(v0, i0, lane, 0, k, j);
            cx_shfl(v1, i1, lane, 32, k, j);
        }
    }
    if (v1 < v0) { float t = v0; v0 = v1; v1 = t; int ti = i0; i0 = i1; i1 = ti; }
#pragma unroll
    for (int j = 16; j >= 1; j >>= 1) {
        cx_shfl(v0, i0, lane, 0, 64, j);
        cx_shfl(v1, i1, lane, 32, 64, j);
    }
}

__device__ __forceinline__ void merge64(float& k0v, int& k0i, float& k1v, int& k1i,
                                        float b0v, int b0i, float b1v, int b1i, int lane) {
    float r0v = __shfl_xor_sync(0xffffffffu, b1v, 31);
    int   r0i = __shfl_xor_sync(0xffffffffu, b1i, 31);
    float r1v = __shfl_xor_sync(0xffffffffu, b0v, 31);
    int   r1i = __shfl_xor_sync(0xffffffffu, b0i, 31);
    if (r0v < k0v) { k0v = r0v; k0i = r0i; }
    if (r1v < k1v) { k1v = r1v; k1i = r1i; }
    if (k1v < k0v) { float t = k0v; k0v = k1v; k1v = t; int ti = k0i; k0i = k1i; k1i = ti; }
#pragma unroll
    for (int j = 16; j >= 1; j >>= 1) {
        cx_shfl(k0v, k0i, lane, 0, 64, j);
        cx_shfl(k1v, k1i, lane, 32, 64, j);
    }
}

// ---------------- K3: warp-autonomous PQ scan, register top-64 (R11/R13 exact) ----------------
__global__ void __launch_bounds__(512, 4) scan_k(const int* __restrict__ vcodes,
                                                 const float* __restrict__ vcb,
                                                 const float* __restrict__ bias,
                                                 float* __restrict__ out) {
    int b = blockIdx.x;
    int tid = threadIdx.x;
    int lane = tid & 31;
    int w = tid >> 5;                  // 16 warps
    __shared__ float lut_s[2048];      // 8 KB
    __shared__ float bufd[16 * 96];    // 6 KB : per-warp candidate buffer / kept lists
    __shared__ int   bufi[16 * 96];    // 6 KB
    __shared__ float s_w[KTOP];
    __shared__ float s_winv;

    // stage LUT (8 KB)
    ((float4*)lut_s)[tid] = ((const float4*)&g_lut[b * 2048])[tid];
    __syncthreads();

    float* mbd = bufd + w * 96;
    int*   mbi = bufi + w * 96;
    int   cnt = 0;
    float tau = FLT_MAX;
    float k0v = FLT_MAX, k1v = FLT_MAX;   // kept top-64 (registers, sorted asc)
    int   k0i = 0, k1i = 0;
    unsigned lanemask_lt = (1u << lane) - 1u;

    int nbase = w << 12;               // warp stripe: 4096 codes
    unsigned long long c8 = g_codes[nbase + lane];
#pragma unroll 1
    for (int it = 0; it < 128; ++it) {
        int n = nbase + (it << 5) + lane;
        unsigned long long nx = (it < 127) ? g_codes[n + 32] : 0ULL;
        unsigned lo = (unsigned)c8;
        unsigned hi = (unsigned)(c8 >> 32);
        float t0 = lut_s[          (lo         & 255u)];
        float t1 = lut_s[ 256 + ((lo >>  8) & 255u)];
        float t2 = lut_s[ 512 + ((lo >> 16) & 255u)];
        float t3 = lut_s[ 768 +  (lo >> 24)         ];
        float t4 = lut_s[1024 + ( hi         & 255u)];
        float t5 = lut_s[1280 + ((hi >>  8) & 255u)];
        float t6 = lut_s[1536 + ((hi >> 16) & 255u)];
        float t7 = lut_s[1792 +  (hi >> 24)         ];
        float d = ((t0 + t1) + (t2 + t3)) + ((t4 + t5) + (t6 + t7));
        c8 = nx;
        unsigned ball = __ballot_sync(0xffffffffu, d < tau);
        if (d < tau) {
            int pos = cnt + __popc(ball & lanemask_lt);
            mbd[pos] = d; mbi[pos] = n;
        }
        cnt += __popc(ball);
        if (cnt >= 64) {                    // flush: sort batch of 64, merge into kept
            __syncwarp();
            float b0v = mbd[lane], b1v = mbd[32 + lane];
            int   b0i = mbi[lane], b1i = mbi[32 + lane];
            int left = cnt - 64;
            if (lane < left) { mbd[lane] = mbd[64 + lane]; mbi[lane] = mbi[64 + lane]; }
            cnt = left;
            __syncwarp();
            sort64(b0v, b0i, b1v, b1i, lane);
            merge64(k0v, k0i, k1v, k1i, b0v, b0i, b1v, b1i, lane);
            tau = __shfl_sync(0xffffffffu, k1v, 31);
        }
    }
    // final partial flush
    if (cnt > 0) {
        for (int i2 = cnt + lane; i2 < 64; i2 += 32) mbd[i2] = FLT_MAX;
        __syncwarp();
        float b0v = mbd[lane], b1v = mbd[32 + lane];
        int   b0i = mbi[lane], b1i = mbi[32 + lane];
        sort64(b0v, b0i, b1v, b1i, lane);
        merge64(k0v, k0i, k1v, k1i, b0v, b0i, b1v, b1i, lane);
    }
    // publish warp's sorted top-64
    mbd[lane] = k0v;  mbd[32 + lane] = k1v;
    mbi[lane] = k0i;  mbi[32 + lane] = k1i;
    __syncthreads();

    // tournament merge of 16 sorted lists (4 rounds, register merges)
#pragma unroll
    for (int step = 1; step < 16; step <<= 1) {
        if (w * 2 * step < 16) {
            int ia = w * 2 * step, ib = ia + step;
            float a0 = bufd[ia * 96 + lane],      a1 = bufd[ia * 96 + 32 + lane];
            int   x0 = bufi[ia * 96 + lane],      x1 = bufi[ia * 96 + 32 + lane];
            float c0 = bufd[ib * 96 + lane],      c1 = bufd[ib * 96 + 32 + lane];
            int   y0 = bufi[ib * 96 + lane],      y1 = bufi[ib * 96 + 32 + lane];
            merge64(a0, x0, a1, x1, c0, y0, c1, y1, lane);
            bufd[ia * 96 + lane] = a0;  bufd[ia * 96 + 32 + lane] = a1;
            bufi[ia * 96 + lane] = x0;  bufi[ia * 96 + 32 + lane] = x1;
        }
        __syncthreads();
    }
    // final top-64 sorted ascending at bufd[0..63] / bufi[0..63]

    // softmax over -dist (q_sq shift cancels; shift by best dist)
    float d0 = bufd[0];
    if (tid < KTOP) s_w[tid] = expf(d0 - bufd[tid]);
    __syncthreads();
    if (tid == 0) {
        float s = 0.f;
        for (int i = 0; i < KTOP; i++) s += s_w[i];
        s_winv = 1.0f / s;
    }
    __syncthreads();

    // y[b, o] = bias[o] + sum_k w_k * vcb[mv][value_codes[n_k][mv]][dv]
    int o0   = tid << 2;          // 4 outputs per thread (512*4 = 2048)
    int mv   = tid >> 6;          // warp-uniform
    int col4 = (o0 & 255) >> 2;
    float4 acc = *(const float4*)&bias[o0];
    const float4* vcb4 = (const float4*)vcb;
    float winv = s_winv;
#pragma unroll 4
    for (int kk = 0; kk < KTOP; kk++) {
        int n = bufi[kk];
        float wt = s_w[kk] * winv;
        int code = vcodes[n * 8 + mv];
        float4 v = vcb4[(((mv << 8) + code) << 6) + col4];
        acc.x = fmaf(wt, v.x, acc.x);
        acc.y = fmaf(wt, v.y, acc.y);
        acc.z = fmaf(wt, v.z, acc.z);
        acc.w = fmaf(wt, v.w, acc.w);
    }
    *(float4*)&out[b * OUTn + o0] = acc;
}

// ---------------- launch ----------------
extern "C" void kernel_launch(void* const* d_in, const int* in_sizes, int n_in,
                              void* d_out, int out_size) {
    const float* x    = (const float*)d_in[0];   // (B, D)
    const float* W    = (const float*)d_in[1];   // (D, D)
    const float* kcb  = (const float*)d_in[2];   // (M, Ks, DS)
    const float* vcb  = (const float*)d_in[3];   // (MV, Ks, DV)
    const float* bias = (const float*)d_in[4];   // (OUT,)
    const int*   kc   = (const int*)d_in[5];     // (N, M)
    const int*   vc   = (const int*)d_in[6];     // (N, MV)
    float* out = (float*)d_out;                  // (B, OUT)

    pack_codes_k<<<Nn / 256, 256>>>(kc);
    csq_k<<<(Mm * KS * 32) / 256, 256>>>(kcb);
    gemm_tc<<<dim3(Dd / 64, Bq / 64), 128>>>(x, W);
    lut_mma<<<dim3(KS / 64, Bq / 64, Mm), 128>>>(kcb);
    scan_k<<<Bq, 512>>>(vc, vcb, bias, out);
}

// round 17
// speedup vs baseline: 1.0837x; 1.0465x over previous
#include <cuda_runtime.h>
#include <math.h>
#include <float.h>

#define Bq   1024
#define Dd   1024
#define Nn   65536
#define Mm   8
#define KS   256
#define DSs  128
#define OUTn 2048
#define KTOP 64

// ---------------- static device scratch (no dynamic allocation) ----------------
__device__ float g_qa[Bq * Dd];                // 4 MB : q = x @ W
__device__ float g_lut[Bq * Mm * KS];          // 8 MB : lut[b][m][c] = c_sq - 2*cross
__device__ float g_csq[Mm * KS];               // 8 KB
__device__ unsigned long long g_codes[Nn];     // 512 KB : 8 packed u8 codes per n

// ---------------- K0: pack key_codes (N x 8 int32) -> u64 per n ----------------
__global__ void pack_codes_k(const int* __restrict__ kc) {
    int n = blockIdx.x * blockDim.x + threadIdx.x;   // grid exactly N
    unsigned long long v = 0;
#pragma unroll
    for (int m = 0; m < 8; m++)
        v |= (unsigned long long)((unsigned)kc[n * 8 + m] & 255u) << (8 * m);
    g_codes[n] = v;
}

// ---------------- K0b: c_sq[m][c] = ||codebook[m][c]||^2 ----------------
__global__ void csq_k(const float* __restrict__ cb) {
    int g = blockIdx.x * blockDim.x + threadIdx.x;   // 2048 warps exactly
    int w = g >> 5, lane = g & 31;
    const float* r = cb + w * DSs;
    float s = 0.f;
#pragma unroll
    for (int d = lane; d < DSs; d += 32) { float x = r[d]; s = fmaf(x, x, s); }
#pragma unroll
    for (int o = 16; o; o >>= 1) s += __shfl_xor_sync(0xffffffffu, s, o);
    if (lane == 0) g_csq[w] = s;
}

// ================= 3xTF32 tensor-core mma helpers =================
__device__ __forceinline__ unsigned f2tf(float x) {
    unsigned r;
    asm("cvt.rna.tf32.f32 %0, %1;" : "=r"(r) : "f"(x));
    return r;
}

#define MMA_TF32(c, a, b0v, b1v)                                             \
    asm volatile("mma.sync.aligned.m16n8k8.row.col.f32.tf32.tf32.f32 "       \
        "{%0,%1,%2,%3}, {%4,%5,%6,%7}, {%8,%9}, {%0,%1,%2,%3};"              \
        : "+f"((c)[0]), "+f"((c)[1]), "+f"((c)[2]), "+f"((c)[3])             \
        : "r"((a)[0]), "r"((a)[1]), "r"((a)[2]), "r"((a)[3]),                \
          "r"(b0v), "r"(b1v))

#define A_STRIDE 20
#define B_STRIDE 72

// ================= K1: q = x @ W via 3xTF32 mma + k-slice prefetch =================
__global__ void __launch_bounds__(128) gemm_tc(const float* __restrict__ A,
                                               const float* __restrict__ W) {
    __shared__ unsigned Ah[64 * A_STRIDE], Al[64 * A_STRIDE];   // [m][k] pad 20
    __shared__ unsigned Bh[16 * B_STRIDE], Bl[16 * B_STRIDE];   // [k][n] pad 72
    int tid  = threadIdx.x;
    int lane = tid & 31;
    int w    = tid >> 5;
    int m0 = blockIdx.y * 64;
    int n0 = blockIdx.x * 64;
    int wm = (w & 1) * 32;          // warp tile 32x32
    int wn = (w >> 1) * 32;

    float c[2][4][4];
#pragma unroll
    for (int mt = 0; mt < 2; mt++)
#pragma unroll
        for (int nt = 0; nt < 4; nt++)
#pragma unroll
            for (int r = 0; r < 4; r++) c[mt][nt][r] = 0.f;

    int ar = tid >> 2, aq = (tid & 3) * 4;     // A: 32 rows/pass, 4 k-floats
    int br = tid >> 4, bq = (tid & 15) * 4;    // B: 8 rows/pass, 4 n-floats

    // prefetch k0 = 0
    float4 vA[2], vB[2];
#pragma unroll
    for (int p = 0; p < 2; p++) {
        vA[p] = *(const float4*)&A[(m0 + ar + p * 32) * Dd + aq];
        vB[p] = *(const float4*)&W[(br + p * 8) * Dd + n0 + bq];
    }

    for (int k0 = 0; k0 < Dd; k0 += 16) {
        // prefetch next k slice while converting/storing this one
        float4 nA[2], nB[2];
        if (k0 + 16 < Dd) {
#pragma unroll
            for (int p = 0; p < 2; p++) {
                nA[p] = *(const float4*)&A[(m0 + ar + p * 32) * Dd + k0 + 16 + aq];
                nB[p] = *(const float4*)&W[(k0 + 16 + br + p * 8) * Dd + n0 + bq];
            }
        }
#pragma unroll
        for (int p = 0; p < 2; p++) {
            float4 v = vA[p];
            unsigned h0 = f2tf(v.x), h1 = f2tf(v.y), h2 = f2tf(v.z), h3 = f2tf(v.w);
            unsigned l0 = f2tf(v.x - __uint_as_float(h0));
            unsigned l1 = f2tf(v.y - __uint_as_float(h1));
            unsigned l2 = f2tf(v.z - __uint_as_float(h2));
            unsigned l3 = f2tf(v.w - __uint_as_float(h3));
            int base = (ar + p * 32) * A_STRIDE + aq;
            Ah[base + 0] = h0; Ah[base + 1] = h1; Ah[base + 2] = h2; Ah[base + 3] = h3;
            Al[base + 0] = l0; Al[base + 1] = l1; Al[base + 2] = l2; Al[base + 3] = l3;
        }
#pragma unroll
        for (int p = 0; p < 2; p++) {
            float4 v = vB[p];
            unsigned h0 = f2tf(v.x), h1 = f2tf(v.y), h2 = f2tf(v.z), h3 = f2tf(v.w);
            unsigned l0 = f2tf(v.x - __uint_as_float(h0));
            unsigned l1 = f2tf(v.y - __uint_as_float(h1));
            unsigned l2 = f2tf(v.z - __uint_as_float(h2));
            unsigned l3 = f2tf(v.w - __uint_as_float(h3));
            int base = (br + p * 8) * B_STRIDE + bq;
            Bh[base + 0] = h0; Bh[base + 1] = h1; Bh[base + 2] = h2; Bh[base + 3] = h3;
            Bl[base + 0] = l0; Bl[base + 1] = l1; Bl[base + 2] = l2; Bl[base + 3] = l3;
        }
        __syncthreads();

#pragma unroll
        for (int ks = 0; ks < 2; ks++) {
            int kb = ks * 8;
            unsigned ah[2][4], al[2][4];
#pragma unroll
            for (int mt = 0; mt < 2; mt++) {
                int r0 = wm + mt * 16 + (lane >> 2);
                int k  = kb + (lane & 3);
                ah[mt][0] = Ah[ r0      * A_STRIDE + k    ];
                ah[mt][1] = Ah[(r0 + 8) * A_STRIDE + k    ];
                ah[mt][2] = Ah[ r0      * A_STRIDE + k + 4];
                ah[mt][3] = Ah[(r0 + 8) * A_STRIDE + k + 4];
                al[mt][0] = Al[ r0      * A_STRIDE + k    ];
                al[mt][1] = Al[(r0 + 8) * A_STRIDE + k    ];
                al[mt][2] = Al[ r0      * A_STRIDE + k + 4];
                al[mt][3] = Al[(r0 + 8) * A_STRIDE + k + 4];
            }
#pragma unroll
            for (int nt = 0; nt < 4; nt++) {
                int cb = wn + nt * 8 + (lane >> 2);
                int kr = kb + (lane & 3);
                unsigned bh0 = Bh[ kr      * B_STRIDE + cb];
                unsigned bh1 = Bh[(kr + 4) * B_STRIDE + cb];
                unsigned bl0 = Bl[ kr      * B_STRIDE + cb];
                unsigned bl1 = Bl[(kr + 4) * B_STRIDE + cb];
#pragma unroll
                for (int mt = 0; mt < 2; mt++) {
                    MMA_TF32(c[mt][nt], ah[mt], bh0, bh1);   // hi*hi
                    MMA_TF32(c[mt][nt], ah[mt], bl0, bl1);   // hi*lo
                    MMA_TF32(c[mt][nt], al[mt], bh0, bh1);   // lo*hi
                }
            }
        }
        __syncthreads();
#pragma unroll
        for (int p = 0; p < 2; p++) { vA[p] = nA[p]; vB[p] = nB[p]; }
    }

    // epilogue: D m16n8 layout -> g_qa
#pragma unroll
    for (int mt = 0; mt < 2; mt++)
#pragma unroll
        for (int nt = 0; nt < 4; nt++) {
            int row = m0 + wm + mt * 16 + (lane >> 2);
            int col = n0 + wn + nt * 8 + (lane & 3) * 2;
            *(float2*)&g_qa[row * Dd + col]       = make_float2(c[mt][nt][0], c[mt][nt][1]);
            *(float2*)&g_qa[(row + 8) * Dd + col] = make_float2(c[mt][nt][2], c[mt][nt][3]);
        }
}

// ================= K2: lut via 3xTF32 mma (R13 exact) =================
__global__ void __launch_bounds__(128) lut_mma(const float* __restrict__ cbk) {
    __shared__ unsigned Ah[64 * A_STRIDE], Al[64 * A_STRIDE];   // q tile   [row][k] pad 20
    __shared__ unsigned Ch[64 * A_STRIDE], Cl[64 * A_STRIDE];   // cb tile  [c][k]   pad 20
    int tid  = threadIdx.x;
    int lane = tid & 31;
    int w    = tid >> 5;
    int m  = blockIdx.z;
    int b0 = blockIdx.y * 64;
    int c0 = blockIdx.x * 64;
    int wm = (w & 1) * 32;
    int wn = (w >> 1) * 32;

    float c[2][4][4];
#pragma unroll
    for (int mt = 0; mt < 2; mt++)
#pragma unroll
        for (int nt = 0; nt < 4; nt++)
#pragma unroll
            for (int r = 0; r < 4; r++) c[mt][nt][r] = 0.f;

    int ar = tid >> 2, aq = (tid & 3) * 4;     // 32 rows/pass, 4 k-floats/thread
    const float* cbm = cbk + m * KS * DSs;

    for (int k0 = 0; k0 < DSs; k0 += 16) {
#pragma unroll
        for (int p = 0; p < 2; p++) {
            int r = ar + p * 32;
            float4 v = *(const float4*)&g_qa[(b0 + r) * Dd + m * DSs + k0 + aq];
            unsigned h0 = f2tf(v.x), h1 = f2tf(v.y), h2 = f2tf(v.z), h3 = f2tf(v.w);
            unsigned l0 = f2tf(v.x - __uint_as_float(h0));
            unsigned l1 = f2tf(v.y - __uint_as_float(h1));
            unsigned l2 = f2tf(v.z - __uint_as_float(h2));
            unsigned l3 = f2tf(v.w - __uint_as_float(h3));
            int base = r * A_STRIDE + aq;
            Ah[base + 0] = h0; Ah[base + 1] = h1; Ah[base + 2] = h2; Ah[base + 3] = h3;
            Al[base + 0] = l0; Al[base + 1] = l1; Al[base + 2] = l2; Al[base + 3] = l3;
            float4 u = *(const float4*)&cbm[(c0 + r) * DSs + k0 + aq];
            unsigned g0 = f2tf(u.x), g1 = f2tf(u.y), g2 = f2tf(u.z), g3 = f2tf(u.w);
            unsigned e0 = f2tf(u.x - __uint_as_float(g0));
            unsigned e1 = f2tf(u.y - __uint_as_float(g1));
            unsigned e2 = f2tf(u.z - __uint_as_float(g2));
            unsigned e3 = f2tf(u.w - __uint_as_float(g3));
            Ch[base + 0] = g0; Ch[base + 1] = g1; Ch[base + 2] = g2; Ch[base + 3] = g3;
            Cl[base + 0] = e0; Cl[base + 1] = e1; Cl[base + 2] = e2; Cl[base + 3] = e3;
        }
        __syncthreads();

#pragma unroll
        for (int ks = 0; ks < 2; ks++) {
            int kb = ks * 8;
            unsigned ah[2][4], al[2][4];
#pragma unroll
            for (int mt = 0; mt < 2; mt++) {
                int r0 = wm + mt * 16 + (lane >> 2);
                int k  = kb + (lane & 3);
                ah[mt][0] = Ah[ r0      * A_STRIDE + k    ];
                ah[mt][1] = Ah[(r0 + 8) * A_STRIDE + k    ];
                ah[mt][2] = Ah[ r0      * A_STRIDE + k + 4];
                ah[mt][3] = Ah[(r0 + 8) * A_STRIDE + k + 4];
                al[mt][0] = Al[ r0      * A_STRIDE + k    ];
                al[mt][1] = Al[(r0 + 8) * A_STRIDE + k    ];
                al[mt][2] = Al[ r0      * A_STRIDE + k + 4];
                al[mt][3] = Al[(r0 + 8) * A_STRIDE + k + 4];
            }
#pragma unroll
            for (int nt = 0; nt < 4; nt++) {
                int cc = wn + nt * 8 + (lane >> 2);
                int kr = kb + (lane & 3);
                unsigned bh0 = Ch[cc * A_STRIDE + kr    ];
                unsigned bh1 = Ch[cc * A_STRIDE + kr + 4];
                unsigned bl0 = Cl[cc * A_STRIDE + kr    ];
                unsigned bl1 = Cl[cc * A_STRIDE + kr + 4];
#pragma unroll
                for (int mt = 0; mt < 2; mt++) {
                    MMA_TF32(c[mt][nt], ah[mt], bh0, bh1);
                    MMA_TF32(c[mt][nt], ah[mt], bl0, bl1);
                    MMA_TF32(c[mt][nt], al[mt], bh0, bh1);
                }
            }
        }
        __syncthreads();
    }

    // epilogue: lut = csq - 2*cross
#pragma unroll
    for (int mt = 0; mt < 2; mt++)
#pragma unroll
        for (int nt = 0; nt < 4; nt++) {
            int row = b0 + wm + mt * 16 + (lane >> 2);
            int col = c0 + wn + nt * 8 + (lane & 3) * 2;
            float2 s = *(const float2*)&g_csq[m * KS + col];
            *(float2*)&g_lut[row * OUTn + m * KS + col] =
                make_float2(s.x - 2.f * c[mt][nt][0], s.y - 2.f * c[mt][nt][1]);
            *(float2*)&g_lut[(row + 8) * OUTn + m * KS + col] =
                make_float2(s.x - 2.f * c[mt][nt][2], s.y - 2.f * c[mt][nt][3]);
        }
}

// ================= register/shfl bitonic top-64 machinery =================
__device__ __forceinline__ void cx_shfl(float& v, int& i, int lane, int ehi, int k, int j) {
    float pv = __shfl_xor_sync(0xffffffffu, v, j);
    int   pi = __shfl_xor_sync(0xffffffffu, i, j);
    bool up = (((ehi + lane) & k) == 0);
    bool keep_min = (up == ((lane & j) == 0));
    if ((pv < v) == keep_min) { v = pv; i = pi; }
}

__device__ __forceinline__ void sort64(float& v0, int& i0, float& v1, int& i1, int lane) {
#pragma unroll
    for (int k = 2; k <= 32; k <<= 1) {
#pragma unroll
        for (int j = k >> 1; j >= 1; j >>= 1) {
            cx_shfl(v0, i0, lane, 0, k, j);
            cx_shfl(v1, i1, lane, 32, k, j);
        }
    }
    if (v1 < v0) { float t = v0; v0 = v1; v1 = t; int ti = i0; i0 = i1; i1 = ti; }
#pragma unroll
    for (int j = 16; j >= 1; j >>= 1) {
        cx_shfl(v0, i0, lane, 0, 64, j);
        cx_shfl(v1, i1, lane, 32, 64, j);
    }
}

__device__ __forceinline__ void merge64(float& k0v, int& k0i, float& k1v, int& k1i,
                                        float b0v, int b0i, float b1v, int b1i, int lane) {
    float r0v = __shfl_xor_sync(0xffffffffu, b1v, 31);
    int   r0i = __shfl_xor_sync(0xffffffffu, b1i, 31);
    float r1v = __shfl_xor_sync(0xffffffffu, b0v, 31);
    int   r1i = __shfl_xor_sync(0xffffffffu, b0i, 31);
    if (r0v < k0v) { k0v = r0v; k0i = r0i; }
    if (r1v < k1v) { k1v = r1v; k1i = r1i; }
    if (k1v < k0v) { float t = k0v; k0v = k1v; k1v = t; int ti = k0i; k0i = k1i; k1i = ti; }
#pragma unroll
    for (int j = 16; j >= 1; j >>= 1) {
        cx_shfl(k0v, k0i, lane, 0, 64, j);
        cx_shfl(k1v, k1i, lane, 32, 64, j);
    }
}

// ---------------- K3: warp-autonomous PQ scan, register top-64 (R13 exact) ----------------
__global__ void __launch_bounds__(512, 4) scan_k(const int* __restrict__ vcodes,
                                                 const float* __restrict__ vcb,
                                                 const float* __restrict__ bias,
                                                 float* __restrict__ out) {
    int b = blockIdx.x;
    int tid = threadIdx.x;
    int lane = tid & 31;
    int w = tid >> 5;                  // 16 warps
    __shared__ float lut_s[2048];      // 8 KB
    __shared__ float bufd[16 * 96];    // 6 KB : per-warp candidate buffer / kept lists
    __shared__ int   bufi[16 * 96];    // 6 KB
    __shared__ float s_w[KTOP];
    __shared__ float s_winv;

    // stage LUT (8 KB)
    ((float4*)lut_s)[tid] = ((const float4*)&g_lut[b * 2048])[tid];
    __syncthreads();

    float* mbd = bufd + w * 96;
    int*   mbi = bufi + w * 96;
    int   cnt = 0;
    float tau = FLT_MAX;
    float k0v = FLT_MAX, k1v = FLT_MAX;   // kept top-64 (registers, sorted asc)
    int   k0i = 0, k1i = 0;
    unsigned lanemask_lt = (1u << lane) - 1u;

    int nbase = w << 12;               // warp stripe: 4096 codes
    unsigned long long c8 = g_codes[nbase + lane];
#pragma unroll 1
    for (int it = 0; it < 128; ++it) {
        int n = nbase + (it << 5) + lane;
        unsigned long long nx = (it < 127) ? g_codes[n + 32] : 0ULL;
        unsigned lo = (unsigned)c8;
        unsigned hi = (unsigned)(c8 >> 32);
        float t0 = lut_s[          (lo         & 255u)];
        float t1 = lut_s[ 256 + ((lo >>  8) & 255u)];
        float t2 = lut_s[ 512 + ((lo >> 16) & 255u)];
        float t3 = lut_s[ 768 +  (lo >> 24)         ];
        float t4 = lut_s[1024 + ( hi         & 255u)];
        float t5 = lut_s[1280 + ((hi >>  8) & 255u)];
        float t6 = lut_s[1536 + ((hi >> 16) & 255u)];
        float t7 = lut_s[1792 +  (hi >> 24)         ];
        float d = ((t0 + t1) + (t2 + t3)) + ((t4 + t5) + (t6 + t7));
        c8 = nx;
        unsigned ball = __ballot_sync(0xffffffffu, d < tau);
        if (d < tau) {
            int pos = cnt + __popc(ball & lanemask_lt);
            mbd[pos] = d; mbi[pos] = n;
        }
        cnt += __popc(ball);
        if (cnt >= 64) {                    // flush: sort batch of 64, merge into kept
            __syncwarp();
            float b0v = mbd[lane], b1v = mbd[32 + lane];
            int   b0i = mbi[lane], b1i = mbi[32 + lane];
            int left = cnt - 64;
            if (lane < left) { mbd[lane] = mbd[64 + lane]; mbi[lane] = mbi[64 + lane]; }
            cnt = left;
            __syncwarp();
            sort64(b0v, b0i, b1v, b1i, lane);
            merge64(k0v, k0i, k1v, k1i, b0v, b0i, b1v, b1i, lane);
            tau = __shfl_sync(0xffffffffu, k1v, 31);
        }
    }
    // final partial flush
    if (cnt > 0) {
        for (int i2 = cnt + lane; i2 < 64; i2 += 32) mbd[i2] = FLT_MAX;
        __syncwarp();
        float b0v = mbd[lane], b1v = mbd[32 + lane];
        int   b0i = mbi[lane], b1i = mbi[32 + lane];
        sort64(b0v, b0i, b1v, b1i, lane);
        merge64(k0v, k0i, k1v, k1i, b0v, b0i, b1v, b1i, lane);
    }
    // publish warp's sorted top-64
    mbd[lane] = k0v;  mbd[32 + lane] = k1v;
    mbi[lane] = k0i;  mbi[32 + lane] = k1i;
    __syncthreads();

    // tournament merge of 16 sorted lists (4 rounds, register merges)
#pragma unroll
    for (int step = 1; step < 16; step <<= 1) {
        if (w * 2 * step < 16) {
            int ia = w * 2 * step, ib = ia + step;
            float a0 = bufd[ia * 96 + lane],      a1 = bufd[ia * 96 + 32 + lane];
            int   x0 = bufi[ia * 96 + lane],      x1 = bufi[ia * 96 + 32 + lane];
            float c0 = bufd[ib * 96 + lane],      c1 = bufd[ib * 96 + 32 + lane];
            int   y0 = bufi[ib * 96 + lane],      y1 = bufi[ib * 96 + 32 + lane];
            merge64(a0, x0, a1, x1, c0, y0, c1, y1, lane);
            bufd[ia * 96 + lane] = a0;  bufd[ia * 96 + 32 + lane] = a1;
            bufi[ia * 96 + lane] = x0;  bufi[ia * 96 + 32 + lane] = x1;
        }
        __syncthreads();
    }
    // final top-64 sorted ascending at bufd[0..63] / bufi[0..63]

    // softmax over -dist (q_sq shift cancels; shift by best dist)
    float d0 = bufd[0];
    if (tid < KTOP) s_w[tid] = expf(d0 - bufd[tid]);
    __syncthreads();
    if (tid == 0) {
        float s = 0.f;
        for (int i = 0; i < KTOP; i++) s += s_w[i];
        s_winv = 1.0f / s;
    }
    __syncthreads();

    // y[b, o] = bias[o] + sum_k w_k * vcb[mv][value_codes[n_k][mv]][dv]
    int o0   = tid << 2;          // 4 outputs per thread (512*4 = 2048)
    int mv   = tid >> 6;          // warp-uniform
    int col4 = (o0 & 255) >> 2;
    float4 acc = *(const float4*)&bias[o0];
    const float4* vcb4 = (const float4*)vcb;
    float winv = s_winv;
#pragma unroll 4
    for (int kk = 0; kk < KTOP; kk++) {
        int n = bufi[kk];
        float wt = s_w[kk] * winv;
        int code = vcodes[n * 8 + mv];
        float4 v = vcb4[(((mv << 8) + code) << 6) + col4];
        acc.x = fmaf(wt, v.x, acc.x);
        acc.y = fmaf(wt, v.y, acc.y);
        acc.z = fmaf(wt, v.z, acc.z);
        acc.w = fmaf(wt, v.w, acc.w);
    }
    *(float4*)&out[b * OUTn + o0] = acc;
}

// ---------------- launch ----------------
extern "C" void kernel_launch(void* const* d_in, const int* in_sizes, int n_in,
                              void* d_out, int out_size) {
    const float* x    = (const float*)d_in[0];   // (B, D)
    const float* W    = (const float*)d_in[1];   // (D, D)
    const float* kcb  = (const float*)d_in[2];   // (M, Ks, DS)
    const float* vcb  = (const float*)d_in[3];   // (MV, Ks, DV)
    const float* bias = (const float*)d_in[4];   // (OUT,)
    const int*   kc   = (const int*)d_in[5];     // (N, M)
    const int*   vc   = (const int*)d_in[6];     // (N, MV)
    float* out = (float*)d_out;                  // (B, OUT)

    pack_codes_k<<<Nn / 256, 256>>>(kc);
    csq_k<<<(Mm * KS * 32) / 256, 256>>>(kcb);
    gemm_tc<<<dim3(Dd / 64, Bq / 64), 128>>>(x, W);
    lut_mma<<<dim3(KS / 64, Bq / 64, Mm), 128>>>(kcb);
    scan_k<<<Bq, 512>>>(vc, vcb, bias, out);
}